// round 14
// baseline (speedup 1.0000x reference)
#include <cuda_runtime.h>
#include <cuda_fp16.h>
#include <cstdint>
#include <cstddef>

#define NBATCH 8
#define CFEAT  256
#define NGROUP 8
#define NTOT   21760
#define KTOP   100
#define GNEPS  1e-5f
#define NCB    170
#define NSEG   680

__device__ float   g_h[(size_t)NBATCH * CFEAT * NTOT];
__device__ float   g_logits[NBATCH * NTOT];
__device__ double2 g_part1[4 * NBATCH * NGROUP * 8];
__device__ double2 g_part2[NBATCH * NGROUP * NCB];
__device__ float   g_a1[4 * NBATCH * CFEAT];
__device__ float   g_d1[4 * NBATCH * CFEAT];
__device__ float   g_a2[4 * NBATCH * CFEAT];
__device__ float   g_d2[4 * NBATCH * CFEAT];
__device__ uint2   g_bsplit[(size_t)NBATCH * NTOT * 128];   // [b][px][kpair-permuted]
__device__ uint2   g_asplit[256 * 128];                     // [o][kpair-permuted]

__device__ __forceinline__ uint32_t pack_h2(float x, float y) {
    __half2 p = __halves2half2(__float2half_rn(x), __float2half_rn(y));
    return *reinterpret_cast<uint32_t*>(&p);
}
__device__ __forceinline__ uint2 split2(float v0, float v1) {
    float h0 = __half2float(__float2half_rn(v0));
    float h1 = __half2float(__float2half_rn(v1));
    uint2 r;
    r.x = pack_h2(h0, h1);
    r.y = pack_h2(v0 - h0, v1 - h1);
    return r;
}
// kpair permutation: within each k16 group (8 kpairs), pair (c, c+4) stored adjacently.
__device__ __forceinline__ int kp_perm(int kp) {
    const int grp = kp >> 3, w = kp & 7;
    return grp * 8 + (((w & 3) << 1) | (w >> 2));
}
__device__ __forceinline__ void mma_f16(float* d, uint32_t a0, uint32_t a1, uint32_t a2,
                                        uint32_t a3, uint32_t b0, uint32_t b1) {
    asm volatile(
        "mma.sync.aligned.m16n8k16.row.col.f32.f16.f16.f32 "
        "{%0,%1,%2,%3}, {%4,%5,%6,%7}, {%8,%9}, {%0,%1,%2,%3};"
        : "+f"(d[0]), "+f"(d[1]), "+f"(d[2]), "+f"(d[3])
        : "r"(a0), "r"(a1), "r"(a2), "r"(a3), "r"(b0), "r"(b1));
}
__device__ __forceinline__ uint4 lds128(uint32_t a) {
    uint4 r;
    asm volatile("ld.shared.v4.u32 {%0,%1,%2,%3}, [%4];"
                 : "=r"(r.x), "=r"(r.y), "=r"(r.z), "=r"(r.w) : "r"(a));
    return r;
}
#define CP_ASYNC16(dst, src) \
    asm volatile("cp.async.cg.shared.global [%0], [%1], 16;" :: "r"(dst), "l"(src))
#define CP_COMMIT() asm volatile("cp.async.commit_group;" ::: "memory")
#define CP_WAIT1()  asm volatile("cp.async.wait_group 1;" ::: "memory")

// ---------------- GN1 stats (merged) + W1 split tail blocks ----------------
__global__ __launch_bounds__(256)
void stats_all_kernel(const float* __restrict__ x0, const float* __restrict__ x1,
                      const float* __restrict__ x2, const float* __restrict__ x3,
                      double2* __restrict__ part1,
                      const float* __restrict__ W1, uint2* __restrict__ ag)
{
    int bi = blockIdx.x;
    const int tid = threadIdx.x;
    if (bi >= 768) {   // asplit tail
        const int idx = (bi - 768) * 256 + tid;
        const int o = idx >> 7, kp = idx & 127;
        float w0 = W1[o * 256 + kp * 2];
        float w1 = W1[o * 256 + kp * 2 + 1];
        ag[o * 128 + kp_perm(kp)] = split2(w0, w1);
        return;
    }
    int lev, nchLog, L;
    const float* src;
    if (bi < 512)      { lev = 0; nchLog = 3; L = 16384; src = x0; }
    else if (bi < 640) { lev = 1; nchLog = 1; L = 4096;  src = x1; bi -= 512; }
    else if (bi < 704) { lev = 2; nchLog = 0; L = 1024;  src = x2; bi -= 640; }
    else               { lev = 3; nchLog = 0; L = 256;   src = x3; bi -= 704; }
    const int nch = 1 << nchLog;
    const int ch = bi & (nch - 1);
    const int bg = bi >> nchLog;
    const int b = bg >> 3, g = bg & 7;
    const int chunk = L >> nchLog;
    const int q0 = (ch * chunk) >> 2, q1 = ((ch + 1) * chunk) >> 2;

    float s = 0.f, q = 0.f;
    for (int c = 0; c < 32; ++c) {
        const float4* row = (const float4*)(src + (size_t)(b * CFEAT + g * 32 + c) * L);
        for (int i = q0 + tid; i < q1; i += 256) {
            float4 v = row[i];
            s += (v.x + v.y) + (v.z + v.w);
            q += (v.x * v.x + v.y * v.y) + (v.z * v.z + v.w * v.w);
        }
    }
#pragma unroll
    for (int off = 16; off; off >>= 1) {
        s += __shfl_down_sync(0xffffffffu, s, off);
        q += __shfl_down_sync(0xffffffffu, q, off);
    }
    __shared__ float ws[8], wq[8];
    if ((tid & 31) == 0) { ws[tid >> 5] = s; wq[tid >> 5] = q; }
    __syncthreads();
    if (tid == 0) {
        double S = 0.0, Q = 0.0;
        for (int w = 0; w < 8; ++w) { S += (double)ws[w]; Q += (double)wq[w]; }
        part1[lev * 512 + (b * NGROUP + g) * 8 + ch] = make_double2(S, Q);
    }
}

__global__ void finalize1_kernel(const double2* __restrict__ part,
                                 const float* __restrict__ scale, const float* __restrict__ bias,
                                 float* __restrict__ aOut, float* __restrict__ dOut)
{
    const int idx = blockIdx.x;
    const int lev = idx >> 6, b = (idx >> 3) & 7, g = idx & 7;
    const int nchs[4] = {8, 2, 1, 1};
    const int Ls[4] = {16384, 4096, 1024, 256};
    double s = 0.0, ss = 0.0;
    for (int ch = 0; ch < nchs[lev]; ++ch) {
        double2 p = part[lev * 512 + (b * NGROUP + g) * 8 + ch];
        s += p.x; ss += p.y;
    }
    const double cnt = 32.0 * (double)Ls[lev];
    const double mu = s / cnt;
    const float var = (float)(ss / cnt - mu * mu);
    const float rinv = rsqrtf(var + GNEPS);
    const int c = g * 32 + threadIdx.x;
    const float a = scale[c] * rinv;
    aOut[(lev * NBATCH + b) * CFEAT + c] = a;
    dOut[(lev * NBATCH + b) * CFEAT + c] = bias[c] - (float)mu * a;
}

// ---------------- B split: relu(GN1(x)) -> [b][px][kpair-permuted] ----------------
__global__ __launch_bounds__(256)
void bsplit_kernel(const float* __restrict__ x0, const float* __restrict__ x1,
                   const float* __restrict__ x2, const float* __restrict__ x3,
                   const float* __restrict__ a1, const float* __restrict__ d1,
                   uint2* __restrict__ bgout)
{
    __shared__ float v[32][65];
    __shared__ float sa[256], sd[256];
    const int tid = threadIdx.x;
    const int b = blockIdx.y;
    const int px0 = blockIdx.x * 64;
    int lev, L, loff;
    const float* xs;
    if (px0 < 16384)      { lev = 0; L = 16384; loff = 0;     xs = x0; }
    else if (px0 < 20480) { lev = 1; L = 4096;  loff = 16384; xs = x1; }
    else if (px0 < 21504) { lev = 2; L = 1024;  loff = 20480; xs = x2; }
    else                  { lev = 3; L = 256;   loff = 21504; xs = x3; }
    const int pxl = px0 - loff;

    sa[tid] = a1[(lev * NBATCH + b) * CFEAT + tid];
    sd[tid] = d1[(lev * NBATCH + b) * CFEAT + tid];
    __syncthreads();

    uint2* outBase = bgout + ((size_t)b * NTOT + px0) * 128;

    for (int cb = 0; cb < 8; ++cb) {
        const int chL = tid >> 3;
        const int ch = cb * 32 + chL;
        const int pxq = (tid & 7) * 8;
        const float* row = xs + ((size_t)b * CFEAT + ch) * L + pxl + pxq;
        float4 u0 = *(const float4*)row;
        float4 u1 = *(const float4*)(row + 4);
        const float a = sa[ch], d = sd[ch];
        v[chL][pxq + 0] = fmaxf(fmaf(a, u0.x, d), 0.f);
        v[chL][pxq + 1] = fmaxf(fmaf(a, u0.y, d), 0.f);
        v[chL][pxq + 2] = fmaxf(fmaf(a, u0.z, d), 0.f);
        v[chL][pxq + 3] = fmaxf(fmaf(a, u0.w, d), 0.f);
        v[chL][pxq + 4] = fmaxf(fmaf(a, u1.x, d), 0.f);
        v[chL][pxq + 5] = fmaxf(fmaf(a, u1.y, d), 0.f);
        v[chL][pxq + 6] = fmaxf(fmaf(a, u1.z, d), 0.f);
        v[chL][pxq + 7] = fmaxf(fmaf(a, u1.w, d), 0.f);
        __syncthreads();
#pragma unroll
        for (int it = 0; it < 4; ++it) {
            const int idx = it * 256 + tid;
            const int px = idx >> 4, cp = idx & 15;
            uint2 r = split2(v[cp * 2][px], v[cp * 2 + 1][px]);
            outBase[(size_t)px * 128 + kp_perm(cb * 16 + cp)] = r;
        }
        __syncthreads();
    }
}

// ---------------- fp16x3 GEMM: k32 chunks, 3-stage cp.async, fully unrolled ----------------
// dynamic smem: 3 stages x 32KB. Stage layout: A-sub0 8K | A-sub1 8K | B-sub0 8K | B-sub1 8K.
// Sub-arrays are 64B rows (round-11 verified conflict-free fragment addressing).
#define STAGE_SZ 32768u
#define GEMM_SMEM (3 * STAGE_SZ)

__global__ __launch_bounds__(256, 2)
void gemm_f16_kernel(const uint2* __restrict__ ag, const uint2* __restrict__ bg,
                     const float* __restrict__ b1, float* __restrict__ hbase,
                     double2* __restrict__ part2)
{
    extern __shared__ char dynsmem[];
    __shared__ float redS[8], redQ[8];

    const int tid = threadIdx.x, wid = tid >> 5, lane = tid & 31;
    const int colTile = blockIdx.x, om2 = blockIdx.y, b = blockIdx.z;
    const int om = om2 * 128;
    const int wm = (wid & 3) * 32, wn = (wid >> 2) * 64;
    const int g = lane >> 2, c = lane & 3;

    const bool isB = tid >= 128;
    const int srow = tid & 127;
    // global row = 1024B (128 kpairs x 8B); chunk slice = 128B at chunk*128
    const char* srcRow = (const char*)(isB
        ? (bg + ((size_t)b * NTOT + colTile * 128 + srow) * 128)
        : (ag + (size_t)(om + srow) * 128));
    const uint32_t sbase = (uint32_t)__cvta_generic_to_shared(dynsmem);
    // dst within stage: sub0 at (isB?16384:0), sub1 at +8192
    const uint32_t dRow0 = sbase + (isB ? 16384u : 0u) + (uint32_t)srow * 64u;

    float acc[2][8][4];
#pragma unroll
    for (int i = 0; i < 2; ++i)
#pragma unroll
        for (int j = 0; j < 8; ++j)
#pragma unroll
            for (int t = 0; t < 4; ++t) acc[i][j][t] = 0.f;

    // stage one chunk: global 128B slice -> sub0 first 64B, sub1 second 64B
#define STAGE_CHUNK(CH, ST) do { \
        const uint32_t d0 = dRow0 + (ST) * STAGE_SZ; \
        const char* s = srcRow + (CH) * 128; \
        CP_ASYNC16(d0,          s);       CP_ASYNC16(d0 + 16,        s + 16); \
        CP_ASYNC16(d0 + 32,     s + 32);  CP_ASYNC16(d0 + 48,        s + 48); \
        CP_ASYNC16(d0 + 8192,   s + 64);  CP_ASYNC16(d0 + 8192 + 16, s + 80); \
        CP_ASYNC16(d0 + 8192 + 32, s + 96); CP_ASYNC16(d0 + 8192 + 48, s + 112); \
    } while (0)

    STAGE_CHUNK(0, 0); CP_COMMIT();
    STAGE_CHUNK(1, 1); CP_COMMIT();

    const uint32_t aF = sbase + (uint32_t)(wm + g) * 64u + (uint32_t)c * 16u;
    const uint32_t bF = sbase + 16384u + (uint32_t)(wn + g) * 64u + (uint32_t)c * 16u;

#pragma unroll
    for (int chunk = 0; chunk < 8; ++chunk) {
        const uint32_t stOff = (uint32_t)(chunk % 3) * STAGE_SZ;
        CP_WAIT1();
        __syncthreads();
        if (chunk + 2 < 8) {
            STAGE_CHUNK(chunk + 2, (chunk + 2) % 3);
        }
        CP_COMMIT();
#pragma unroll
        for (int s2 = 0; s2 < 2; ++s2) {          // two k16 sub-steps
            const uint32_t sub = stOff + (uint32_t)s2 * 8192u;
            uint4 ua[2][2];
#pragma unroll
            for (int i = 0; i < 2; ++i) {
                ua[i][0] = lds128(aF + sub + (uint32_t)(i * 16) * 64u);
                ua[i][1] = lds128(aF + sub + (uint32_t)(i * 16 + 8) * 64u);
            }
#pragma unroll
            for (int j = 0; j < 8; ++j) {
                uint4 ub = lds128(bF + sub + (uint32_t)(j * 8) * 64u);
#pragma unroll
                for (int i = 0; i < 2; ++i) {
                    mma_f16(acc[i][j], ua[i][0].x, ua[i][1].x, ua[i][0].z, ua[i][1].z, ub.x, ub.z);
                    mma_f16(acc[i][j], ua[i][0].y, ua[i][1].y, ua[i][0].w, ua[i][1].w, ub.x, ub.z);
                    mma_f16(acc[i][j], ua[i][0].x, ua[i][1].x, ua[i][0].z, ua[i][1].z, ub.y, ub.w);
                }
            }
        }
        __syncthreads();
    }

    // epilogue: +bias, write h, fused GN2 partial stats
    float s = 0.f, q = 0.f;
    const int pxBase = colTile * 128;
#pragma unroll
    for (int i = 0; i < 2; ++i) {
        const int r0 = om + wm + i * 16 + g;
        const int r1 = r0 + 8;
        const float bb0 = b1[r0], bb1 = b1[r1];
        float* h0 = hbase + (size_t)(b * 256 + r0) * NTOT + pxBase;
        float* h1 = hbase + (size_t)(b * 256 + r1) * NTOT + pxBase;
#pragma unroll
        for (int j = 0; j < 8; ++j) {
            const int cn = wn + j * 8 + 2 * c;
            float v0 = acc[i][j][0] + bb0, v1 = acc[i][j][1] + bb0;
            float v2 = acc[i][j][2] + bb1, v3 = acc[i][j][3] + bb1;
            *(float2*)&h0[cn] = make_float2(v0, v1);
            *(float2*)&h1[cn] = make_float2(v2, v3);
            s += (v0 + v1) + (v2 + v3);
            q += v0 * v0 + v1 * v1 + v2 * v2 + v3 * v3;
        }
    }
#pragma unroll
    for (int off = 16; off; off >>= 1) {
        s += __shfl_down_sync(0xffffffffu, s, off);
        q += __shfl_down_sync(0xffffffffu, q, off);
    }
    if (lane == 0) { redS[wid] = s; redQ[wid] = q; }
    __syncthreads();
    if (tid < 4) {
        const int grp = om2 * 4 + tid;
        const double S = (double)redS[tid] + (double)redS[tid + 4];
        const double Q = (double)redQ[tid] + (double)redQ[tid + 4];
        part2[(size_t)(b * NGROUP + grp) * NCB + colTile] = make_double2(S, Q);
    }
}

// ---------------- finalize GN2 ----------------
__global__ void finalize2_kernel(const double2* __restrict__ part2,
                                 const float* __restrict__ scale, const float* __restrict__ bias,
                                 float* __restrict__ aOut, float* __restrict__ dOut)
{
    const int idx = blockIdx.x;
    const int lev = idx >> 6, b = (idx >> 3) & 7, g = idx & 7;
    const int cbS[5] = {0, 128, 160, 168, 170};
    const int Ls[4] = {16384, 4096, 1024, 256};
    double s = 0.0, ss = 0.0;
    for (int cb = cbS[lev]; cb < cbS[lev + 1]; ++cb) {
        double2 p = part2[(size_t)(b * NGROUP + g) * NCB + cb];
        s += p.x; ss += p.y;
    }
    const double cnt = 32.0 * (double)Ls[lev];
    const double mu = s / cnt;
    const float var = (float)(ss / cnt - mu * mu);
    const float rinv = rsqrtf(var + GNEPS);
    const int c = g * 32 + threadIdx.x;
    const float a = scale[c] * rinv;
    aOut[(lev * NBATCH + b) * CFEAT + c] = a;
    dOut[(lev * NBATCH + b) * CFEAT + c] = bias[c] - (float)mu * a;
}

// ---------------- logits ----------------
__global__ __launch_bounds__(256)
void logits_kernel(const float* __restrict__ h, const float* __restrict__ a2,
                   const float* __restrict__ d2, const float* __restrict__ W2,
                   const float* __restrict__ b2, float* __restrict__ logits,
                   float* __restrict__ outLog, int colOff, int L)
{
    __shared__ float sa[256], sd[256], sw[256];
    const int tid = threadIdx.x;
    const int b = blockIdx.y;
    sa[tid] = a2[b * 256 + tid];
    sd[tid] = d2[b * 256 + tid];
    sw[tid] = W2[tid];
    __syncthreads();

    const int rel = blockIdx.x * 1024 + tid * 4;
    if (rel >= L) return;
    const int pos = colOff + rel;
    const float* hp = h + (size_t)b * 256 * NTOT + pos;
    const float bb = b2[0];
    float4 acc = make_float4(bb, bb, bb, bb);
#pragma unroll 4
    for (int c = 0; c < 256; ++c) {
        float4 v = *(const float4*)&hp[(size_t)c * NTOT];
        const float w = sw[c], a = sa[c], d = sd[c];
        acc.x = fmaf(w, fmaxf(fmaf(a, v.x, d), 0.f), acc.x);
        acc.y = fmaf(w, fmaxf(fmaf(a, v.y, d), 0.f), acc.y);
        acc.z = fmaf(w, fmaxf(fmaf(a, v.z, d), 0.f), acc.z);
        acc.w = fmaf(w, fmaxf(fmaf(a, v.w, d), 0.f), acc.w);
    }
    *(float4*)&logits[b * NTOT + pos] = acc;
    if (outLog) *(float4*)&outLog[b * NTOT + pos] = acc;
}

// ---------------- segmented top-100 ----------------
__device__ __forceinline__ unsigned ford(float f) {
    unsigned u = __float_as_uint(f);
    return (u & 0x80000000u) ? ~u : (u | 0x80000000u);
}

__global__ __launch_bounds__(1024)
void topk_kernel(const float* __restrict__ logits, float* __restrict__ outF, int* __restrict__ outI)
{
    extern __shared__ float sv[];
    float* segMax = sv + NTOT;
    __shared__ unsigned long long warpRes[32];
    __shared__ int winSeg;
    const int b = blockIdx.x, tid = threadIdx.x;
    const int lane = tid & 31, wid = tid >> 5;
    const float NEGINF = __int_as_float(0xff800000);

    for (int i = tid; i < NTOT; i += 1024) sv[i] = logits[b * NTOT + i];
    __syncthreads();
    if (tid < NSEG) {
        float m = NEGINF;
        for (int j = 0; j < 32; ++j) m = fmaxf(m, sv[tid * 32 + j]);
        segMax[tid] = m;
    }
    __syncthreads();

    for (int k = 0; k < KTOP; ++k) {
        unsigned long long key = 0ull;
        if (tid < NSEG)
            key = ((unsigned long long)ford(segMax[tid]) << 32) | (unsigned)(NSEG - 1 - tid);
#pragma unroll
        for (int off = 16; off; off >>= 1) {
            unsigned long long o = __shfl_down_sync(0xffffffffu, key, off);
            key = (o > key) ? o : key;
        }
        if (lane == 0) warpRes[wid] = key;
        __syncthreads();
        if (wid == 0) {
            unsigned long long v = warpRes[lane];
#pragma unroll
            for (int off = 16; off; off >>= 1) {
                unsigned long long o = __shfl_down_sync(0xffffffffu, v, off);
                v = (o > v) ? o : v;
            }
            if (lane == 0) winSeg = NSEG - 1 - (int)(v & 0xffffffffu);
        }
        __syncthreads();
        if (wid == 0) {
            const int s = winSeg;
            float v = sv[s * 32 + lane];
            unsigned long long r = ((unsigned long long)ford(v) << 32) | (unsigned)(31 - lane);
#pragma unroll
            for (int off = 16; off; off >>= 1) {
                unsigned long long o = __shfl_xor_sync(0xffffffffu, r, off);
                r = (o > r) ? o : r;
            }
            const int wl = 31 - (int)(r & 31u);
            if (lane == wl) {
                const int idx = s * 32 + wl;
                if (outF) outF[b * KTOP + k] = (float)idx;
                if (outI) outI[b * KTOP + k] = idx;
                sv[idx] = NEGINF;
                v = NEGINF;
            }
            float m = v;
#pragma unroll
            for (int off = 16; off; off >>= 1)
                m = fmaxf(m, __shfl_xor_sync(0xffffffffu, m, off));
            if (lane == 0) segMax[s] = m;
        }
        __syncthreads();
    }
}

// ---------------- host launcher ----------------
extern "C" void kernel_launch(void* const* d_in, const int* in_sizes, int n_in,
                              void* d_out, int out_size)
{
    (void)in_sizes; (void)n_in;
    const float* xs[4] = {(const float*)d_in[0], (const float*)d_in[1],
                          (const float*)d_in[2], (const float*)d_in[3]};
    const float* gn1_scale = (const float*)d_in[4];
    const float* gn1_bias  = (const float*)d_in[5];
    const float* W1        = (const float*)d_in[6];
    const float* b1        = (const float*)d_in[7];
    const float* gn2_scale = (const float*)d_in[8];
    const float* gn2_bias  = (const float*)d_in[9];
    const float* W2        = (const float*)d_in[10];
    const float* b2        = (const float*)d_in[11];

    const int Ls[4]   = {16384, 4096, 1024, 256};
    const int offs[4] = {0, 16384, 20480, 21504};

    void* tmp;
    cudaGetSymbolAddress(&tmp, g_h);      float*   p_h    = (float*)tmp;
    cudaGetSymbolAddress(&tmp, g_logits); float*   p_log  = (float*)tmp;
    cudaGetSymbolAddress(&tmp, g_part1);  double2* p_p1   = (double2*)tmp;
    cudaGetSymbolAddress(&tmp, g_part2);  double2* p_p2   = (double2*)tmp;
    cudaGetSymbolAddress(&tmp, g_a1);     float*   p_a1   = (float*)tmp;
    cudaGetSymbolAddress(&tmp, g_d1);     float*   p_d1   = (float*)tmp;
    cudaGetSymbolAddress(&tmp, g_a2);     float*   p_a2   = (float*)tmp;
    cudaGetSymbolAddress(&tmp, g_d2);     float*   p_d2   = (float*)tmp;
    cudaGetSymbolAddress(&tmp, g_bsplit); uint2*   p_bg   = (uint2*)tmp;
    cudaGetSymbolAddress(&tmp, g_asplit); uint2*   p_ag   = (uint2*)tmp;

    float* outF   = (float*)d_out;
    float* outLog = nullptr;
    float* outIdF = nullptr;
    int*   outIdI = nullptr;
    const int NIDS = NBATCH * KTOP;
    const int NLOG = NBATCH * NTOT;
    if (out_size >= NIDS + NLOG)      { outIdF = outF; outLog = outF + NIDS; }
    else if (out_size == NLOG)        { outLog = outF; }
    else if (out_size == NIDS)        { outIdI = (int*)d_out; }
    else                              { outIdF = outF; if (out_size > NIDS) outLog = outF + NIDS; }

    stats_all_kernel<<<896, 256>>>(xs[0], xs[1], xs[2], xs[3], p_p1, W1, p_ag);
    finalize1_kernel<<<4 * NBATCH * NGROUP, 32>>>(p_p1, gn1_scale, gn1_bias, p_a1, p_d1);
    bsplit_kernel<<<dim3(NTOT / 64, NBATCH), 256>>>(xs[0], xs[1], xs[2], xs[3], p_a1, p_d1, p_bg);

    cudaFuncSetAttribute(gemm_f16_kernel, cudaFuncAttributeMaxDynamicSharedMemorySize, GEMM_SMEM);
    gemm_f16_kernel<<<dim3(NCB, 2, NBATCH), 256, GEMM_SMEM>>>(p_ag, p_bg, b1, p_h, p_p2);

    finalize2_kernel<<<4 * NBATCH * NGROUP, 32>>>(p_p2, gn2_scale, gn2_bias, p_a2, p_d2);

    for (int lev = 0; lev < 4; ++lev) {
        const int nblk = (Ls[lev] + 1023) / 1024;
        logits_kernel<<<dim3(nblk, NBATCH), 256>>>(
            p_h, p_a2 + lev * NBATCH * CFEAT, p_d2 + lev * NBATCH * CFEAT,
            W2, b2, p_log, outLog, offs[lev], Ls[lev]);
    }

    const int tkSmem = (NTOT + NSEG) * 4;
    cudaFuncSetAttribute(topk_kernel, cudaFuncAttributeMaxDynamicSharedMemorySize, tkSmem);
    topk_kernel<<<NBATCH, 1024, tkSmem>>>(p_log, outIdF, outIdI);
}

// round 15
// speedup vs baseline: 1.3034x; 1.3034x over previous
#include <cuda_runtime.h>
#include <cuda_fp16.h>
#include <cstdint>
#include <cstddef>

#define NBATCH 8
#define CFEAT  256
#define NGROUP 8
#define NTOT   21760
#define KTOP   100
#define GNEPS  1e-5f
#define NCB    170
#define NSEG   680

__device__ float   g_h[(size_t)NBATCH * CFEAT * NTOT];
__device__ float   g_logits[NBATCH * NTOT];
__device__ double2 g_part1[4 * NBATCH * NGROUP * 8];
__device__ double2 g_part2[NBATCH * NGROUP * NCB];
__device__ float   g_a1[4 * NBATCH * CFEAT];
__device__ float   g_d1[4 * NBATCH * CFEAT];
__device__ float   g_a2[4 * NBATCH * CFEAT];
__device__ float   g_d2[4 * NBATCH * CFEAT];
__device__ uint2   g_bsplit[(size_t)NBATCH * NTOT * 128];   // [b][px][kpair-permuted]
__device__ uint2   g_asplit[256 * 128];                     // [o][kpair-permuted]

__device__ __forceinline__ uint32_t pack_h2(float x, float y) {
    __half2 p = __halves2half2(__float2half_rn(x), __float2half_rn(y));
    return *reinterpret_cast<uint32_t*>(&p);
}
__device__ __forceinline__ uint2 split2(float v0, float v1) {
    float h0 = __half2float(__float2half_rn(v0));
    float h1 = __half2float(__float2half_rn(v1));
    uint2 r;
    r.x = pack_h2(h0, h1);
    r.y = pack_h2(v0 - h0, v1 - h1);
    return r;
}
__device__ __forceinline__ int kp_perm(int kp) {
    const int grp = kp >> 3, w = kp & 7;
    return grp * 8 + (((w & 3) << 1) | (w >> 2));
}
__device__ __forceinline__ void mma_f16(float* d, uint32_t a0, uint32_t a1, uint32_t a2,
                                        uint32_t a3, uint32_t b0, uint32_t b1) {
    asm volatile(
        "mma.sync.aligned.m16n8k16.row.col.f32.f16.f16.f32 "
        "{%0,%1,%2,%3}, {%4,%5,%6,%7}, {%8,%9}, {%0,%1,%2,%3};"
        : "+f"(d[0]), "+f"(d[1]), "+f"(d[2]), "+f"(d[3])
        : "r"(a0), "r"(a1), "r"(a2), "r"(a3), "r"(b0), "r"(b1));
}
__device__ __forceinline__ uint4 lds128(uint32_t a) {
    uint4 r;
    asm volatile("ld.shared.v4.u32 {%0,%1,%2,%3}, [%4];"
                 : "=r"(r.x), "=r"(r.y), "=r"(r.z), "=r"(r.w) : "r"(a));
    return r;
}
#define CP_ASYNC16(dst, src) \
    asm volatile("cp.async.cg.shared.global [%0], [%1], 16;" :: "r"(dst), "l"(src))
#define CP_COMMIT() asm volatile("cp.async.commit_group;" ::: "memory")
#define CP_WAIT1()  asm volatile("cp.async.wait_group 1;" ::: "memory")

// ---------------- GN1 stats (merged) + W1 split tail ----------------
__global__ __launch_bounds__(256)
void stats_all_kernel(const float* __restrict__ x0, const float* __restrict__ x1,
                      const float* __restrict__ x2, const float* __restrict__ x3,
                      double2* __restrict__ part1,
                      const float* __restrict__ W1, uint2* __restrict__ ag)
{
    int bi = blockIdx.x;
    const int tid = threadIdx.x;
    if (bi >= 768) {
        const int idx = (bi - 768) * 256 + tid;
        const int o = idx >> 7, kp = idx & 127;
        float w0 = W1[o * 256 + kp * 2];
        float w1 = W1[o * 256 + kp * 2 + 1];
        ag[o * 128 + kp_perm(kp)] = split2(w0, w1);
        return;
    }
    int lev, nchLog, L;
    const float* src;
    if (bi < 512)      { lev = 0; nchLog = 3; L = 16384; src = x0; }
    else if (bi < 640) { lev = 1; nchLog = 1; L = 4096;  src = x1; bi -= 512; }
    else if (bi < 704) { lev = 2; nchLog = 0; L = 1024;  src = x2; bi -= 640; }
    else               { lev = 3; nchLog = 0; L = 256;   src = x3; bi -= 704; }
    const int nch = 1 << nchLog;
    const int ch = bi & (nch - 1);
    const int bg = bi >> nchLog;
    const int b = bg >> 3, g = bg & 7;
    const int chunk = L >> nchLog;
    const int q0 = (ch * chunk) >> 2, q1 = ((ch + 1) * chunk) >> 2;

    float s = 0.f, q = 0.f;
    for (int c = 0; c < 32; ++c) {
        const float4* row = (const float4*)(src + (size_t)(b * CFEAT + g * 32 + c) * L);
        for (int i = q0 + tid; i < q1; i += 256) {
            float4 v = row[i];
            s += (v.x + v.y) + (v.z + v.w);
            q += (v.x * v.x + v.y * v.y) + (v.z * v.z + v.w * v.w);
        }
    }
#pragma unroll
    for (int off = 16; off; off >>= 1) {
        s += __shfl_down_sync(0xffffffffu, s, off);
        q += __shfl_down_sync(0xffffffffu, q, off);
    }
    __shared__ float ws[8], wq[8];
    if ((tid & 31) == 0) { ws[tid >> 5] = s; wq[tid >> 5] = q; }
    __syncthreads();
    if (tid == 0) {
        double S = 0.0, Q = 0.0;
        for (int w = 0; w < 8; ++w) { S += (double)ws[w]; Q += (double)wq[w]; }
        part1[lev * 512 + (b * NGROUP + g) * 8 + ch] = make_double2(S, Q);
    }
}

__global__ void finalize1_kernel(const double2* __restrict__ part,
                                 const float* __restrict__ scale, const float* __restrict__ bias,
                                 float* __restrict__ aOut, float* __restrict__ dOut)
{
    const int idx = blockIdx.x;
    const int lev = idx >> 6, b = (idx >> 3) & 7, g = idx & 7;
    const int nchs[4] = {8, 2, 1, 1};
    const int Ls[4] = {16384, 4096, 1024, 256};
    double s = 0.0, ss = 0.0;
    for (int ch = 0; ch < nchs[lev]; ++ch) {
        double2 p = part[lev * 512 + (b * NGROUP + g) * 8 + ch];
        s += p.x; ss += p.y;
    }
    const double cnt = 32.0 * (double)Ls[lev];
    const double mu = s / cnt;
    const float var = (float)(ss / cnt - mu * mu);
    const float rinv = rsqrtf(var + GNEPS);
    const int c = g * 32 + threadIdx.x;
    const float a = scale[c] * rinv;
    aOut[(lev * NBATCH + b) * CFEAT + c] = a;
    dOut[(lev * NBATCH + b) * CFEAT + c] = bias[c] - (float)mu * a;
}

// ---------------- B split ----------------
__global__ __launch_bounds__(256)
void bsplit_kernel(const float* __restrict__ x0, const float* __restrict__ x1,
                   const float* __restrict__ x2, const float* __restrict__ x3,
                   const float* __restrict__ a1, const float* __restrict__ d1,
                   uint2* __restrict__ bgout)
{
    __shared__ float v[32][65];
    __shared__ float sa[256], sd[256];
    const int tid = threadIdx.x;
    const int b = blockIdx.y;
    const int px0 = blockIdx.x * 64;
    int lev, L, loff;
    const float* xs;
    if (px0 < 16384)      { lev = 0; L = 16384; loff = 0;     xs = x0; }
    else if (px0 < 20480) { lev = 1; L = 4096;  loff = 16384; xs = x1; }
    else if (px0 < 21504) { lev = 2; L = 1024;  loff = 20480; xs = x2; }
    else                  { lev = 3; L = 256;   loff = 21504; xs = x3; }
    const int pxl = px0 - loff;

    sa[tid] = a1[(lev * NBATCH + b) * CFEAT + tid];
    sd[tid] = d1[(lev * NBATCH + b) * CFEAT + tid];
    __syncthreads();

    uint2* outBase = bgout + ((size_t)b * NTOT + px0) * 128;

    for (int cb = 0; cb < 8; ++cb) {
        const int chL = tid >> 3;
        const int ch = cb * 32 + chL;
        const int pxq = (tid & 7) * 8;
        const float* row = xs + ((size_t)b * CFEAT + ch) * L + pxl + pxq;
        float4 u0 = *(const float4*)row;
        float4 u1 = *(const float4*)(row + 4);
        const float a = sa[ch], d = sd[ch];
        v[chL][pxq + 0] = fmaxf(fmaf(a, u0.x, d), 0.f);
        v[chL][pxq + 1] = fmaxf(fmaf(a, u0.y, d), 0.f);
        v[chL][pxq + 2] = fmaxf(fmaf(a, u0.z, d), 0.f);
        v[chL][pxq + 3] = fmaxf(fmaf(a, u0.w, d), 0.f);
        v[chL][pxq + 4] = fmaxf(fmaf(a, u1.x, d), 0.f);
        v[chL][pxq + 5] = fmaxf(fmaf(a, u1.y, d), 0.f);
        v[chL][pxq + 6] = fmaxf(fmaf(a, u1.z, d), 0.f);
        v[chL][pxq + 7] = fmaxf(fmaf(a, u1.w, d), 0.f);
        __syncthreads();
#pragma unroll
        for (int it = 0; it < 4; ++it) {
            const int idx = it * 256 + tid;
            const int px = idx >> 4, cp = idx & 15;
            uint2 r = split2(v[cp * 2][px], v[cp * 2 + 1][px]);
            outBase[(size_t)px * 128 + kp_perm(cb * 16 + cp)] = r;
        }
        __syncthreads();
    }
}

// ---------------- fp16x3 GEMM (round-11 variant, measured 351us) ----------------
__global__ __launch_bounds__(256, 2)
void gemm_f16_kernel(const uint2* __restrict__ ag, const uint2* __restrict__ bg,
                     const float* __restrict__ b1, float* __restrict__ hbase,
                     double2* __restrict__ part2)
{
    extern __shared__ char dynsmem[];
    __shared__ float redS[8], redQ[8];

    const int tid = threadIdx.x, wid = tid >> 5, lane = tid & 31;
    const int colTile = blockIdx.x, om2 = blockIdx.y, b = blockIdx.z;
    const int om = om2 * 128;
    const int wm = (wid & 3) * 32, wn = (wid >> 2) * 64;
    const int g = lane >> 2, c = lane & 3;

    const bool isB = tid >= 128;
    const int srow = tid & 127;
    const char* srcBase = (const char*)(isB
        ? (bg + ((size_t)b * NTOT + colTile * 128 + srow) * 128)
        : (ag + (size_t)(om + srow) * 128));
    const uint32_t sbase = (uint32_t)__cvta_generic_to_shared(dynsmem);
    const uint32_t dstRow = sbase + (isB ? 8192u : 0u) + (uint32_t)srow * 64u;

    float acc[2][8][4];
#pragma unroll
    for (int i = 0; i < 2; ++i)
#pragma unroll
        for (int j = 0; j < 8; ++j)
#pragma unroll
            for (int t = 0; t < 4; ++t) acc[i][j][t] = 0.f;

#pragma unroll
    for (int p = 0; p < 2; ++p) {
        const uint32_t d = dstRow + p * 16384u;
        const char* s = srcBase + p * 64;
        CP_ASYNC16(d, s); CP_ASYNC16(d + 16, s + 16);
        CP_ASYNC16(d + 32, s + 32); CP_ASYNC16(d + 48, s + 48);
        CP_COMMIT();
    }

    const uint32_t aFragBase = sbase + (uint32_t)(wm) * 64u;
    const uint32_t bFragBase = sbase + 8192u + (uint32_t)(wn) * 64u;

#pragma unroll 1
    for (int chunk = 0; chunk < 16; ++chunk) {
        const int stage = chunk % 3;
        const uint32_t stOff = (uint32_t)stage * 16384u;
        CP_WAIT1();
        __syncthreads();

        uint4 ua[2][2];
#pragma unroll
        for (int i = 0; i < 2; ++i) {
            ua[i][0] = lds128(aFragBase + stOff + (uint32_t)(i * 16 + g) * 64u + c * 16u);
            ua[i][1] = lds128(aFragBase + stOff + (uint32_t)(i * 16 + g + 8) * 64u + c * 16u);
        }
#pragma unroll
        for (int j = 0; j < 8; ++j) {
            uint4 ub = lds128(bFragBase + stOff + (uint32_t)(j * 8 + g) * 64u + c * 16u);
#pragma unroll
            for (int i = 0; i < 2; ++i) {
                mma_f16(acc[i][j], ua[i][0].x, ua[i][1].x, ua[i][0].z, ua[i][1].z, ub.x, ub.z);
                mma_f16(acc[i][j], ua[i][0].y, ua[i][1].y, ua[i][0].w, ua[i][1].w, ub.x, ub.z);
                mma_f16(acc[i][j], ua[i][0].x, ua[i][1].x, ua[i][0].z, ua[i][1].z, ub.y, ub.w);
            }
        }
        if (chunk + 2 < 16) {
            const int ns = (chunk + 2) % 3;
            const uint32_t d = dstRow + (uint32_t)ns * 16384u;
            const char* s = srcBase + (chunk + 2) * 64;
            CP_ASYNC16(d, s); CP_ASYNC16(d + 16, s + 16);
            CP_ASYNC16(d + 32, s + 32); CP_ASYNC16(d + 48, s + 48);
        }
        CP_COMMIT();
    }

    float s = 0.f, q = 0.f;
    const int pxBase = colTile * 128;
#pragma unroll
    for (int i = 0; i < 2; ++i) {
        const int r0 = om + wm + i * 16 + g;
        const int r1 = r0 + 8;
        const float bb0 = b1[r0], bb1 = b1[r1];
        float* h0 = hbase + (size_t)(b * 256 + r0) * NTOT + pxBase;
        float* h1 = hbase + (size_t)(b * 256 + r1) * NTOT + pxBase;
#pragma unroll
        for (int j = 0; j < 8; ++j) {
            const int cn = wn + j * 8 + 2 * c;
            float v0 = acc[i][j][0] + bb0, v1 = acc[i][j][1] + bb0;
            float v2 = acc[i][j][2] + bb1, v3 = acc[i][j][3] + bb1;
            *(float2*)&h0[cn] = make_float2(v0, v1);
            *(float2*)&h1[cn] = make_float2(v2, v3);
            s += (v0 + v1) + (v2 + v3);
            q += v0 * v0 + v1 * v1 + v2 * v2 + v3 * v3;
        }
    }
#pragma unroll
    for (int off = 16; off; off >>= 1) {
        s += __shfl_down_sync(0xffffffffu, s, off);
        q += __shfl_down_sync(0xffffffffu, q, off);
    }
    if (lane == 0) { redS[wid] = s; redQ[wid] = q; }
    __syncthreads();
    if (tid < 4) {
        const int grp = om2 * 4 + tid;
        const double S = (double)redS[tid] + (double)redS[tid + 4];
        const double Q = (double)redQ[tid] + (double)redQ[tid + 4];
        part2[(size_t)(b * NGROUP + grp) * NCB + colTile] = make_double2(S, Q);
    }
}

// ---------------- finalize GN2 ----------------
__global__ void finalize2_kernel(const double2* __restrict__ part2,
                                 const float* __restrict__ scale, const float* __restrict__ bias,
                                 float* __restrict__ aOut, float* __restrict__ dOut)
{
    const int idx = blockIdx.x;
    const int lev = idx >> 6, b = (idx >> 3) & 7, g = idx & 7;
    const int cbS[5] = {0, 128, 160, 168, 170};
    const int Ls[4] = {16384, 4096, 1024, 256};
    double s = 0.0, ss = 0.0;
    for (int cb = cbS[lev]; cb < cbS[lev + 1]; ++cb) {
        double2 p = part2[(size_t)(b * NGROUP + g) * NCB + cb];
        s += p.x; ss += p.y;
    }
    const double cnt = 32.0 * (double)Ls[lev];
    const double mu = s / cnt;
    const float var = (float)(ss / cnt - mu * mu);
    const float rinv = rsqrtf(var + GNEPS);
    const int c = g * 32 + threadIdx.x;
    const float a = scale[c] * rinv;
    aOut[(lev * NBATCH + b) * CFEAT + c] = a;
    dOut[(lev * NBATCH + b) * CFEAT + c] = bias[c] - (float)mu * a;
}

// ---------------- logits: merged, high-occupancy, 4-way channel split ----------------
// 85 x 8 blocks; block covers 256 px; thread-group grp handles channels [grp*64, grp*64+64)
__global__ __launch_bounds__(256)
void logits_kernel(const float* __restrict__ h, const float* __restrict__ a2base,
                   const float* __restrict__ d2base, const float* __restrict__ W2,
                   const float* __restrict__ b2, float* __restrict__ logits,
                   float* __restrict__ outLog)
{
    __shared__ float sa[256], sd[256], sw[256];
    __shared__ float4 partial[4][64];
    const int tid = threadIdx.x;
    const int b = blockIdx.y;
    const int px0 = blockIdx.x * 256;
    int lev;
    if (px0 < 16384)      lev = 0;
    else if (px0 < 20480) lev = 1;
    else if (px0 < 21504) lev = 2;
    else                  lev = 3;

    sa[tid] = a2base[(lev * NBATCH + b) * CFEAT + tid];
    sd[tid] = d2base[(lev * NBATCH + b) * CFEAT + tid];
    sw[tid] = W2[tid];
    __syncthreads();

    const int grp = tid >> 6;            // 0..3
    const int px4 = tid & 63;            // 0..63
    const int pos = px0 + px4 * 4;
    const float* hp = h + ((size_t)(b * 256 + grp * 64)) * NTOT + pos;

    float4 acc = make_float4(0.f, 0.f, 0.f, 0.f);
#pragma unroll 8
    for (int c = 0; c < 64; ++c) {
        float4 v = *(const float4*)&hp[(size_t)c * NTOT];
        const int cg = grp * 64 + c;
        const float w = sw[cg], a = sa[cg], d = sd[cg];
        acc.x = fmaf(w, fmaxf(fmaf(a, v.x, d), 0.f), acc.x);
        acc.y = fmaf(w, fmaxf(fmaf(a, v.y, d), 0.f), acc.y);
        acc.z = fmaf(w, fmaxf(fmaf(a, v.z, d), 0.f), acc.z);
        acc.w = fmaf(w, fmaxf(fmaf(a, v.w, d), 0.f), acc.w);
    }
    partial[grp][px4] = acc;
    __syncthreads();
    if (grp == 0) {
        const float bb = b2[0];
        float4 p0 = partial[0][px4], p1 = partial[1][px4];
        float4 p2 = partial[2][px4], p3 = partial[3][px4];
        float4 r = make_float4(bb + ((p0.x + p1.x) + (p2.x + p3.x)),
                               bb + ((p0.y + p1.y) + (p2.y + p3.y)),
                               bb + ((p0.z + p1.z) + (p2.z + p3.z)),
                               bb + ((p0.w + p1.w) + (p2.w + p3.w)));
        *(float4*)&logits[b * NTOT + pos] = r;
        if (outLog) *(float4*)&outLog[b * NTOT + pos] = r;
    }
}

// ---------------- segmented top-100 ----------------
__device__ __forceinline__ unsigned ford(float f) {
    unsigned u = __float_as_uint(f);
    return (u & 0x80000000u) ? ~u : (u | 0x80000000u);
}

__global__ __launch_bounds__(1024)
void topk_kernel(const float* __restrict__ logits, float* __restrict__ outF, int* __restrict__ outI)
{
    extern __shared__ float sv[];
    float* segMax = sv + NTOT;
    __shared__ unsigned long long warpRes[32];
    __shared__ int winSeg;
    const int b = blockIdx.x, tid = threadIdx.x;
    const int lane = tid & 31, wid = tid >> 5;
    const float NEGINF = __int_as_float(0xff800000);

    for (int i = tid; i < NTOT; i += 1024) sv[i] = logits[b * NTOT + i];
    __syncthreads();
    if (tid < NSEG) {
        float m = NEGINF;
        for (int j = 0; j < 32; ++j) m = fmaxf(m, sv[tid * 32 + j]);
        segMax[tid] = m;
    }
    __syncthreads();

    for (int k = 0; k < KTOP; ++k) {
        unsigned long long key = 0ull;
        if (tid < NSEG)
            key = ((unsigned long long)ford(segMax[tid]) << 32) | (unsigned)(NSEG - 1 - tid);
#pragma unroll
        for (int off = 16; off; off >>= 1) {
            unsigned long long o = __shfl_down_sync(0xffffffffu, key, off);
            key = (o > key) ? o : key;
        }
        if (lane == 0) warpRes[wid] = key;
        __syncthreads();
        if (wid == 0) {
            unsigned long long v = warpRes[lane];
#pragma unroll
            for (int off = 16; off; off >>= 1) {
                unsigned long long o = __shfl_down_sync(0xffffffffu, v, off);
                v = (o > v) ? o : v;
            }
            if (lane == 0) winSeg = NSEG - 1 - (int)(v & 0xffffffffu);
        }
        __syncthreads();
        if (wid == 0) {
            const int s = winSeg;
            float v = sv[s * 32 + lane];
            unsigned long long r = ((unsigned long long)ford(v) << 32) | (unsigned)(31 - lane);
#pragma unroll
            for (int off = 16; off; off >>= 1) {
                unsigned long long o = __shfl_xor_sync(0xffffffffu, r, off);
                r = (o > r) ? o : r;
            }
            const int wl = 31 - (int)(r & 31u);
            if (lane == wl) {
                const int idx = s * 32 + wl;
                if (outF) outF[b * KTOP + k] = (float)idx;
                if (outI) outI[b * KTOP + k] = idx;
                sv[idx] = NEGINF;
                v = NEGINF;
            }
            float m = v;
#pragma unroll
            for (int off = 16; off; off >>= 1)
                m = fmaxf(m, __shfl_xor_sync(0xffffffffu, m, off));
            if (lane == 0) segMax[s] = m;
        }
        __syncthreads();
    }
}

// ---------------- host launcher ----------------
extern "C" void kernel_launch(void* const* d_in, const int* in_sizes, int n_in,
                              void* d_out, int out_size)
{
    (void)in_sizes; (void)n_in;
    const float* xs[4] = {(const float*)d_in[0], (const float*)d_in[1],
                          (const float*)d_in[2], (const float*)d_in[3]};
    const float* gn1_scale = (const float*)d_in[4];
    const float* gn1_bias  = (const float*)d_in[5];
    const float* W1        = (const float*)d_in[6];
    const float* b1        = (const float*)d_in[7];
    const float* gn2_scale = (const float*)d_in[8];
    const float* gn2_bias  = (const float*)d_in[9];
    const float* W2        = (const float*)d_in[10];
    const float* b2        = (const float*)d_in[11];

    void* tmp;
    cudaGetSymbolAddress(&tmp, g_h);      float*   p_h    = (float*)tmp;
    cudaGetSymbolAddress(&tmp, g_logits); float*   p_log  = (float*)tmp;
    cudaGetSymbolAddress(&tmp, g_part1);  double2* p_p1   = (double2*)tmp;
    cudaGetSymbolAddress(&tmp, g_part2);  double2* p_p2   = (double2*)tmp;
    cudaGetSymbolAddress(&tmp, g_a1);     float*   p_a1   = (float*)tmp;
    cudaGetSymbolAddress(&tmp, g_d1);     float*   p_d1   = (float*)tmp;
    cudaGetSymbolAddress(&tmp, g_a2);     float*   p_a2   = (float*)tmp;
    cudaGetSymbolAddress(&tmp, g_d2);     float*   p_d2   = (float*)tmp;
    cudaGetSymbolAddress(&tmp, g_bsplit); uint2*   p_bg   = (uint2*)tmp;
    cudaGetSymbolAddress(&tmp, g_asplit); uint2*   p_ag   = (uint2*)tmp;

    float* outF   = (float*)d_out;
    float* outLog = nullptr;
    float* outIdF = nullptr;
    int*   outIdI = nullptr;
    const int NIDS = NBATCH * KTOP;
    const int NLOG = NBATCH * NTOT;
    if (out_size >= NIDS + NLOG)      { outIdF = outF; outLog = outF + NIDS; }
    else if (out_size == NLOG)        { outLog = outF; }
    else if (out_size == NIDS)        { outIdI = (int*)d_out; }
    else                              { outIdF = outF; if (out_size > NIDS) outLog = outF + NIDS; }

    stats_all_kernel<<<896, 256>>>(xs[0], xs[1], xs[2], xs[3], p_p1, W1, p_ag);
    finalize1_kernel<<<4 * NBATCH * NGROUP, 32>>>(p_p1, gn1_scale, gn1_bias, p_a1, p_d1);
    bsplit_kernel<<<dim3(NTOT / 64, NBATCH), 256>>>(xs[0], xs[1], xs[2], xs[3], p_a1, p_d1, p_bg);

    cudaFuncSetAttribute(gemm_f16_kernel, cudaFuncAttributeMaxDynamicSharedMemorySize, 49152);
    gemm_f16_kernel<<<dim3(NCB, 2, NBATCH), 256, 49152>>>(p_ag, p_bg, b1, p_h, p_p2);

    finalize2_kernel<<<4 * NBATCH * NGROUP, 32>>>(p_p2, gn2_scale, gn2_bias, p_a2, p_d2);

    // merged logits: 85 x 8 blocks, 256 px per block
    logits_kernel<<<dim3(NTOT / 256, NBATCH), 256>>>(p_h, p_a2, p_d2, W2, b2, p_log, outLog);

    const int tkSmem = (NTOT + NSEG) * 4;
    cudaFuncSetAttribute(topk_kernel, cudaFuncAttributeMaxDynamicSharedMemorySize, tkSmem);
    topk_kernel<<<NBATCH, 1024, tkSmem>>>(p_log, outIdF, outIdI);
}

// round 16
// speedup vs baseline: 1.3728x; 1.0533x over previous
#include <cuda_runtime.h>
#include <cuda_fp16.h>
#include <cstdint>
#include <cstddef>

#define NBATCH 8
#define CFEAT  256
#define NGROUP 8
#define NTOT   21760
#define KTOP   100
#define GNEPS  1e-5f
#define NCB    170
#define NSEG   680

__device__ float   g_h[(size_t)NBATCH * CFEAT * NTOT];
__device__ float   g_logits[NBATCH * NTOT];
__device__ double2 g_part1[4 * NBATCH * NGROUP * 8];
__device__ double2 g_part2[NBATCH * NGROUP * NCB];
__device__ float   g_a1[4 * NBATCH * CFEAT];
__device__ float   g_d1[4 * NBATCH * CFEAT];
__device__ float   g_a2[4 * NBATCH * CFEAT];
__device__ float   g_d2[4 * NBATCH * CFEAT];
__device__ uint2   g_bsplit[(size_t)NBATCH * NTOT * 128];   // [b][px][kpair-permuted]
__device__ uint2   g_asplit[256 * 128];                     // [o][kpair-permuted]

__device__ __forceinline__ uint32_t pack_h2(float x, float y) {
    __half2 p = __halves2half2(__float2half_rn(x), __float2half_rn(y));
    return *reinterpret_cast<uint32_t*>(&p);
}
__device__ __forceinline__ uint2 split2(float v0, float v1) {
    float h0 = __half2float(__float2half_rn(v0));
    float h1 = __half2float(__float2half_rn(v1));
    uint2 r;
    r.x = pack_h2(h0, h1);
    r.y = pack_h2(v0 - h0, v1 - h1);
    return r;
}
__device__ __forceinline__ int kp_perm(int kp) {
    const int grp = kp >> 3, w = kp & 7;
    return grp * 8 + (((w & 3) << 1) | (w >> 2));
}
__device__ __forceinline__ void mma_f16(float* d, uint32_t a0, uint32_t a1, uint32_t a2,
                                        uint32_t a3, uint32_t b0, uint32_t b1) {
    asm volatile(
        "mma.sync.aligned.m16n8k16.row.col.f32.f16.f16.f32 "
        "{%0,%1,%2,%3}, {%4,%5,%6,%7}, {%8,%9}, {%0,%1,%2,%3};"
        : "+f"(d[0]), "+f"(d[1]), "+f"(d[2]), "+f"(d[3])
        : "r"(a0), "r"(a1), "r"(a2), "r"(a3), "r"(b0), "r"(b1));
}
__device__ __forceinline__ uint4 lds128(uint32_t a) {
    uint4 r;
    asm volatile("ld.shared.v4.u32 {%0,%1,%2,%3}, [%4];"
                 : "=r"(r.x), "=r"(r.y), "=r"(r.z), "=r"(r.w) : "r"(a));
    return r;
}
#define CP_ASYNC16(dst, src) \
    asm volatile("cp.async.cg.shared.global [%0], [%1], 16;" :: "r"(dst), "l"(src))
#define CP_COMMIT() asm volatile("cp.async.commit_group;" ::: "memory")
#define CP_WAIT1()  asm volatile("cp.async.wait_group 1;" ::: "memory")

// ---------------- GN1 stats (merged) + W1 split tail ----------------
__global__ __launch_bounds__(256)
void stats_all_kernel(const float* __restrict__ x0, const float* __restrict__ x1,
                      const float* __restrict__ x2, const float* __restrict__ x3,
                      double2* __restrict__ part1,
                      const float* __restrict__ W1, uint2* __restrict__ ag)
{
    int bi = blockIdx.x;
    const int tid = threadIdx.x;
    if (bi >= 768) {
        const int idx = (bi - 768) * 256 + tid;
        const int o = idx >> 7, kp = idx & 127;
        float w0 = W1[o * 256 + kp * 2];
        float w1 = W1[o * 256 + kp * 2 + 1];
        ag[o * 128 + kp_perm(kp)] = split2(w0, w1);
        return;
    }
    int lev, nchLog, L;
    const float* src;
    if (bi < 512)      { lev = 0; nchLog = 3; L = 16384; src = x0; }
    else if (bi < 640) { lev = 1; nchLog = 1; L = 4096;  src = x1; bi -= 512; }
    else if (bi < 704) { lev = 2; nchLog = 0; L = 1024;  src = x2; bi -= 640; }
    else               { lev = 3; nchLog = 0; L = 256;   src = x3; bi -= 704; }
    const int nch = 1 << nchLog;
    const int ch = bi & (nch - 1);
    const int bg = bi >> nchLog;
    const int b = bg >> 3, g = bg & 7;
    const int chunk = L >> nchLog;
    const int q0 = (ch * chunk) >> 2, q1 = ((ch + 1) * chunk) >> 2;

    float s = 0.f, q = 0.f;
    for (int c = 0; c < 32; ++c) {
        const float4* row = (const float4*)(src + (size_t)(b * CFEAT + g * 32 + c) * L);
        for (int i = q0 + tid; i < q1; i += 256) {
            float4 v = row[i];
            s += (v.x + v.y) + (v.z + v.w);
            q += (v.x * v.x + v.y * v.y) + (v.z * v.z + v.w * v.w);
        }
    }
#pragma unroll
    for (int off = 16; off; off >>= 1) {
        s += __shfl_down_sync(0xffffffffu, s, off);
        q += __shfl_down_sync(0xffffffffu, q, off);
    }
    __shared__ float ws[8], wq[8];
    if ((tid & 31) == 0) { ws[tid >> 5] = s; wq[tid >> 5] = q; }
    __syncthreads();
    if (tid == 0) {
        double S = 0.0, Q = 0.0;
        for (int w = 0; w < 8; ++w) { S += (double)ws[w]; Q += (double)wq[w]; }
        part1[lev * 512 + (b * NGROUP + g) * 8 + ch] = make_double2(S, Q);
    }
}

__global__ void finalize1_kernel(const double2* __restrict__ part,
                                 const float* __restrict__ scale, const float* __restrict__ bias,
                                 float* __restrict__ aOut, float* __restrict__ dOut)
{
    const int idx = blockIdx.x;
    const int lev = idx >> 6, b = (idx >> 3) & 7, g = idx & 7;
    const int nchs[4] = {8, 2, 1, 1};
    const int Ls[4] = {16384, 4096, 1024, 256};
    double s = 0.0, ss = 0.0;
    for (int ch = 0; ch < nchs[lev]; ++ch) {
        double2 p = part[lev * 512 + (b * NGROUP + g) * 8 + ch];
        s += p.x; ss += p.y;
    }
    const double cnt = 32.0 * (double)Ls[lev];
    const double mu = s / cnt;
    const float var = (float)(ss / cnt - mu * mu);
    const float rinv = rsqrtf(var + GNEPS);
    const int c = g * 32 + threadIdx.x;
    const float a = scale[c] * rinv;
    aOut[(lev * NBATCH + b) * CFEAT + c] = a;
    dOut[(lev * NBATCH + b) * CFEAT + c] = bias[c] - (float)mu * a;
}

// ---------------- B split ----------------
__global__ __launch_bounds__(256)
void bsplit_kernel(const float* __restrict__ x0, const float* __restrict__ x1,
                   const float* __restrict__ x2, const float* __restrict__ x3,
                   const float* __restrict__ a1, const float* __restrict__ d1,
                   uint2* __restrict__ bgout)
{
    __shared__ float v[32][65];
    __shared__ float sa[256], sd[256];
    const int tid = threadIdx.x;
    const int b = blockIdx.y;
    const int px0 = blockIdx.x * 64;
    int lev, L, loff;
    const float* xs;
    if (px0 < 16384)      { lev = 0; L = 16384; loff = 0;     xs = x0; }
    else if (px0 < 20480) { lev = 1; L = 4096;  loff = 16384; xs = x1; }
    else if (px0 < 21504) { lev = 2; L = 1024;  loff = 20480; xs = x2; }
    else                  { lev = 3; L = 256;   loff = 21504; xs = x3; }
    const int pxl = px0 - loff;

    sa[tid] = a1[(lev * NBATCH + b) * CFEAT + tid];
    sd[tid] = d1[(lev * NBATCH + b) * CFEAT + tid];
    __syncthreads();

    uint2* outBase = bgout + ((size_t)b * NTOT + px0) * 128;

    for (int cb = 0; cb < 8; ++cb) {
        const int chL = tid >> 3;
        const int ch = cb * 32 + chL;
        const int pxq = (tid & 7) * 8;
        const float* row = xs + ((size_t)b * CFEAT + ch) * L + pxl + pxq;
        float4 u0 = *(const float4*)row;
        float4 u1 = *(const float4*)(row + 4);
        const float a = sa[ch], d = sd[ch];
        v[chL][pxq + 0] = fmaxf(fmaf(a, u0.x, d), 0.f);
        v[chL][pxq + 1] = fmaxf(fmaf(a, u0.y, d), 0.f);
        v[chL][pxq + 2] = fmaxf(fmaf(a, u0.z, d), 0.f);
        v[chL][pxq + 3] = fmaxf(fmaf(a, u0.w, d), 0.f);
        v[chL][pxq + 4] = fmaxf(fmaf(a, u1.x, d), 0.f);
        v[chL][pxq + 5] = fmaxf(fmaf(a, u1.y, d), 0.f);
        v[chL][pxq + 6] = fmaxf(fmaf(a, u1.z, d), 0.f);
        v[chL][pxq + 7] = fmaxf(fmaf(a, u1.w, d), 0.f);
        __syncthreads();
#pragma unroll
        for (int it = 0; it < 4; ++it) {
            const int idx = it * 256 + tid;
            const int px = idx >> 4, cp = idx & 15;
            uint2 r = split2(v[cp * 2][px], v[cp * 2 + 1][px]);
            outBase[(size_t)px * 128 + kp_perm(cb * 16 + cp)] = r;
        }
        __syncthreads();
    }
}

// ---------------- fp16x3 GEMM: 512 threads, 16 warps (8m x 2n), 32-reg accumulators ----------------
// 3-stage cp.async (16KB/stage: A 8KB | B 8KB), 64B rows, kp-perm layout (round-11 verified).
__global__ __launch_bounds__(512, 2)
void gemm_f16_kernel(const uint2* __restrict__ ag, const uint2* __restrict__ bg,
                     const float* __restrict__ b1, float* __restrict__ hbase,
                     double2* __restrict__ part2)
{
    extern __shared__ char dynsmem[];
    __shared__ float redS[16], redQ[16];

    const int tid = threadIdx.x, wid = tid >> 5, lane = tid & 31;
    const int colTile = blockIdx.x, om2 = blockIdx.y, b = blockIdx.z;
    const int om = om2 * 128;
    const int wm = (wid & 7) * 16;      // 8 m-warps
    const int wn = (wid >> 3) * 64;     // 2 n-warps
    const int g = lane >> 2, c = lane & 3;

    // staging: threads 0-255 stage A (2 threads/row), 256-511 stage B
    const bool isB = tid >= 256;
    const int srow = (tid & 255) >> 1;
    const int shalf = tid & 1;          // which 32B half of the 64B chunk-slice
    const char* srcRow = (const char*)(isB
        ? (bg + ((size_t)b * NTOT + colTile * 128 + srow) * 128)
        : (ag + (size_t)(om + srow) * 128)) + shalf * 32;
    const uint32_t sbase = (uint32_t)__cvta_generic_to_shared(dynsmem);
    const uint32_t dstRow = sbase + (isB ? 8192u : 0u) + (uint32_t)srow * 64u + (uint32_t)shalf * 32u;

    float acc[8][4];
#pragma unroll
    for (int j = 0; j < 8; ++j)
#pragma unroll
        for (int t = 0; t < 4; ++t) acc[j][t] = 0.f;

#pragma unroll
    for (int p = 0; p < 2; ++p) {
        const uint32_t d = dstRow + p * 16384u;
        const char* s = srcRow + p * 64;
        CP_ASYNC16(d, s); CP_ASYNC16(d + 16, s + 16);
        CP_COMMIT();
    }

    const uint32_t aF = sbase + (uint32_t)(wm + g) * 64u + (uint32_t)c * 16u;
    const uint32_t bF = sbase + 8192u + (uint32_t)(wn + g) * 64u + (uint32_t)c * 16u;

#pragma unroll 1
    for (int chunk = 0; chunk < 16; ++chunk) {
        const uint32_t stOff = (uint32_t)(chunk % 3) * 16384u;
        CP_WAIT1();
        __syncthreads();

        uint4 ua0 = lds128(aF + stOff);                 // row wm+g
        uint4 ua1 = lds128(aF + stOff + 512u);          // row wm+g+8  (8*64)
#pragma unroll
        for (int j = 0; j < 8; ++j) {
            uint4 ub = lds128(bF + stOff + (uint32_t)(j * 512));
            mma_f16(acc[j], ua0.x, ua1.x, ua0.z, ua1.z, ub.x, ub.z);
            mma_f16(acc[j], ua0.y, ua1.y, ua0.w, ua1.w, ub.x, ub.z);
            mma_f16(acc[j], ua0.x, ua1.x, ua0.z, ua1.z, ub.y, ub.w);
        }
        if (chunk + 2 < 16) {
            const uint32_t d = dstRow + (uint32_t)((chunk + 2) % 3) * 16384u;
            const char* s = srcRow + (chunk + 2) * 64;
            CP_ASYNC16(d, s); CP_ASYNC16(d + 16, s + 16);
        }
        CP_COMMIT();
        __syncthreads();
    }

    // epilogue: +bias, write h, fused GN2 partial stats
    float s = 0.f, q = 0.f;
    const int pxBase = colTile * 128;
    {
        const int r0 = om + wm + g;
        const int r1 = r0 + 8;
        const float bb0 = b1[r0], bb1 = b1[r1];
        float* h0 = hbase + (size_t)(b * 256 + r0) * NTOT + pxBase;
        float* h1 = hbase + (size_t)(b * 256 + r1) * NTOT + pxBase;
#pragma unroll
        for (int j = 0; j < 8; ++j) {
            const int cn = wn + j * 8 + 2 * c;
            float v0 = acc[j][0] + bb0, v1 = acc[j][1] + bb0;
            float v2 = acc[j][2] + bb1, v3 = acc[j][3] + bb1;
            *(float2*)&h0[cn] = make_float2(v0, v1);
            *(float2*)&h1[cn] = make_float2(v2, v3);
            s += (v0 + v1) + (v2 + v3);
            q += v0 * v0 + v1 * v1 + v2 * v2 + v3 * v3;
        }
    }
#pragma unroll
    for (int off = 16; off; off >>= 1) {
        s += __shfl_down_sync(0xffffffffu, s, off);
        q += __shfl_down_sync(0xffffffffu, q, off);
    }
    if (lane == 0) { redS[wid] = s; redQ[wid] = q; }
    __syncthreads();
    if (tid < 4) {
        // group om2*4+t: warps 2t, 2t+1 (n-half 0) and 8+2t, 8+2t+1 (n-half 1)
        const int grp = om2 * 4 + tid;
        const double S = (double)redS[2 * tid] + (double)redS[2 * tid + 1]
                       + (double)redS[2 * tid + 8] + (double)redS[2 * tid + 9];
        const double Q = (double)redQ[2 * tid] + (double)redQ[2 * tid + 1]
                       + (double)redQ[2 * tid + 8] + (double)redQ[2 * tid + 9];
        part2[(size_t)(b * NGROUP + grp) * NCB + colTile] = make_double2(S, Q);
    }
}

// ---------------- finalize GN2 ----------------
__global__ void finalize2_kernel(const double2* __restrict__ part2,
                                 const float* __restrict__ scale, const float* __restrict__ bias,
                                 float* __restrict__ aOut, float* __restrict__ dOut)
{
    const int idx = blockIdx.x;
    const int lev = idx >> 6, b = (idx >> 3) & 7, g = idx & 7;
    const int cbS[5] = {0, 128, 160, 168, 170};
    const int Ls[4] = {16384, 4096, 1024, 256};
    double s = 0.0, ss = 0.0;
    for (int cb = cbS[lev]; cb < cbS[lev + 1]; ++cb) {
        double2 p = part2[(size_t)(b * NGROUP + g) * NCB + cb];
        s += p.x; ss += p.y;
    }
    const double cnt = 32.0 * (double)Ls[lev];
    const double mu = s / cnt;
    const float var = (float)(ss / cnt - mu * mu);
    const float rinv = rsqrtf(var + GNEPS);
    const int c = g * 32 + threadIdx.x;
    const float a = scale[c] * rinv;
    aOut[(lev * NBATCH + b) * CFEAT + c] = a;
    dOut[(lev * NBATCH + b) * CFEAT + c] = bias[c] - (float)mu * a;
}

// ---------------- logits: merged, high-occupancy, 4-way channel split ----------------
__global__ __launch_bounds__(256)
void logits_kernel(const float* __restrict__ h, const float* __restrict__ a2base,
                   const float* __restrict__ d2base, const float* __restrict__ W2,
                   const float* __restrict__ b2, float* __restrict__ logits,
                   float* __restrict__ outLog)
{
    __shared__ float sa[256], sd[256], sw[256];
    __shared__ float4 partial[4][64];
    const int tid = threadIdx.x;
    const int b = blockIdx.y;
    const int px0 = blockIdx.x * 256;
    int lev;
    if (px0 < 16384)      lev = 0;
    else if (px0 < 20480) lev = 1;
    else if (px0 < 21504) lev = 2;
    else                  lev = 3;

    sa[tid] = a2base[(lev * NBATCH + b) * CFEAT + tid];
    sd[tid] = d2base[(lev * NBATCH + b) * CFEAT + tid];
    sw[tid] = W2[tid];
    __syncthreads();

    const int grp = tid >> 6;
    const int px4 = tid & 63;
    const int pos = px0 + px4 * 4;
    const float* hp = h + ((size_t)(b * 256 + grp * 64)) * NTOT + pos;

    float4 acc = make_float4(0.f, 0.f, 0.f, 0.f);
#pragma unroll 8
    for (int c = 0; c < 64; ++c) {
        float4 v = *(const float4*)&hp[(size_t)c * NTOT];
        const int cg = grp * 64 + c;
        const float w = sw[cg], a = sa[cg], d = sd[cg];
        acc.x = fmaf(w, fmaxf(fmaf(a, v.x, d), 0.f), acc.x);
        acc.y = fmaf(w, fmaxf(fmaf(a, v.y, d), 0.f), acc.y);
        acc.z = fmaf(w, fmaxf(fmaf(a, v.z, d), 0.f), acc.z);
        acc.w = fmaf(w, fmaxf(fmaf(a, v.w, d), 0.f), acc.w);
    }
    partial[grp][px4] = acc;
    __syncthreads();
    if (grp == 0) {
        const float bb = b2[0];
        float4 p0 = partial[0][px4], p1 = partial[1][px4];
        float4 p2 = partial[2][px4], p3 = partial[3][px4];
        float4 r = make_float4(bb + ((p0.x + p1.x) + (p2.x + p3.x)),
                               bb + ((p0.y + p1.y) + (p2.y + p3.y)),
                               bb + ((p0.z + p1.z) + (p2.z + p3.z)),
                               bb + ((p0.w + p1.w) + (p2.w + p3.w)));
        *(float4*)&logits[b * NTOT + pos] = r;
        if (outLog) *(float4*)&outLog[b * NTOT + pos] = r;
    }
}

// ---------------- segmented top-100 ----------------
__device__ __forceinline__ unsigned ford(float f) {
    unsigned u = __float_as_uint(f);
    return (u & 0x80000000u) ? ~u : (u | 0x80000000u);
}

__global__ __launch_bounds__(1024)
void topk_kernel(const float* __restrict__ logits, float* __restrict__ outF, int* __restrict__ outI)
{
    extern __shared__ float sv[];
    float* segMax = sv + NTOT;
    __shared__ unsigned long long warpRes[32];
    __shared__ int winSeg;
    const int b = blockIdx.x, tid = threadIdx.x;
    const int lane = tid & 31, wid = tid >> 5;
    const float NEGINF = __int_as_float(0xff800000);

    for (int i = tid; i < NTOT; i += 1024) sv[i] = logits[b * NTOT + i];
    __syncthreads();
    if (tid < NSEG) {
        float m = NEGINF;
        for (int j = 0; j < 32; ++j) m = fmaxf(m, sv[tid * 32 + j]);
        segMax[tid] = m;
    }
    __syncthreads();

    for (int k = 0; k < KTOP; ++k) {
        unsigned long long key = 0ull;
        if (tid < NSEG)
            key = ((unsigned long long)ford(segMax[tid]) << 32) | (unsigned)(NSEG - 1 - tid);
#pragma unroll
        for (int off = 16; off; off >>= 1) {
            unsigned long long o = __shfl_down_sync(0xffffffffu, key, off);
            key = (o > key) ? o : key;
        }
        if (lane == 0) warpRes[wid] = key;
        __syncthreads();
        if (wid == 0) {
            unsigned long long v = warpRes[lane];
#pragma unroll
            for (int off = 16; off; off >>= 1) {
                unsigned long long o = __shfl_down_sync(0xffffffffu, v, off);
                v = (o > v) ? o : v;
            }
            if (lane == 0) winSeg = NSEG - 1 - (int)(v & 0xffffffffu);
        }
        __syncthreads();
        if (wid == 0) {
            const int s = winSeg;
            float v = sv[s * 32 + lane];
            unsigned long long r = ((unsigned long long)ford(v) << 32) | (unsigned)(31 - lane);
#pragma unroll
            for (int off = 16; off; off >>= 1) {
                unsigned long long o = __shfl_xor_sync(0xffffffffu, r, off);
                r = (o > r) ? o : r;
            }
            const int wl = 31 - (int)(r & 31u);
            if (lane == wl) {
                const int idx = s * 32 + wl;
                if (outF) outF[b * KTOP + k] = (float)idx;
                if (outI) outI[b * KTOP + k] = idx;
                sv[idx] = NEGINF;
                v = NEGINF;
            }
            float m = v;
#pragma unroll
            for (int off = 16; off; off >>= 1)
                m = fmaxf(m, __shfl_xor_sync(0xffffffffu, m, off));
            if (lane == 0) segMax[s] = m;
        }
        __syncthreads();
    }
}

// ---------------- host launcher ----------------
extern "C" void kernel_launch(void* const* d_in, const int* in_sizes, int n_in,
                              void* d_out, int out_size)
{
    (void)in_sizes; (void)n_in;
    const float* xs[4] = {(const float*)d_in[0], (const float*)d_in[1],
                          (const float*)d_in[2], (const float*)d_in[3]};
    const float* gn1_scale = (const float*)d_in[4];
    const float* gn1_bias  = (const float*)d_in[5];
    const float* W1        = (const float*)d_in[6];
    const float* b1        = (const float*)d_in[7];
    const float* gn2_scale = (const float*)d_in[8];
    const float* gn2_bias  = (const float*)d_in[9];
    const float* W2        = (const float*)d_in[10];
    const float* b2        = (const float*)d_in[11];

    void* tmp;
    cudaGetSymbolAddress(&tmp, g_h);      float*   p_h    = (float*)tmp;
    cudaGetSymbolAddress(&tmp, g_logits); float*   p_log  = (float*)tmp;
    cudaGetSymbolAddress(&tmp, g_part1);  double2* p_p1   = (double2*)tmp;
    cudaGetSymbolAddress(&tmp, g_part2);  double2* p_p2   = (double2*)tmp;
    cudaGetSymbolAddress(&tmp, g_a1);     float*   p_a1   = (float*)tmp;
    cudaGetSymbolAddress(&tmp, g_d1);     float*   p_d1   = (float*)tmp;
    cudaGetSymbolAddress(&tmp, g_a2);     float*   p_a2   = (float*)tmp;
    cudaGetSymbolAddress(&tmp, g_d2);     float*   p_d2   = (float*)tmp;
    cudaGetSymbolAddress(&tmp, g_bsplit); uint2*   p_bg   = (uint2*)tmp;
    cudaGetSymbolAddress(&tmp, g_asplit); uint2*   p_ag   = (uint2*)tmp;

    float* outF   = (float*)d_out;
    float* outLog = nullptr;
    float* outIdF = nullptr;
    int*   outIdI = nullptr;
    const int NIDS = NBATCH * KTOP;
    const int NLOG = NBATCH * NTOT;
    if (out_size >= NIDS + NLOG)      { outIdF = outF; outLog = outF + NIDS; }
    else if (out_size == NLOG)        { outLog = outF; }
    else if (out_size == NIDS)        { outIdI = (int*)d_out; }
    else                              { outIdF = outF; if (out_size > NIDS) outLog = outF + NIDS; }

    stats_all_kernel<<<896, 256>>>(xs[0], xs[1], xs[2], xs[3], p_p1, W1, p_ag);
    finalize1_kernel<<<4 * NBATCH * NGROUP, 32>>>(p_p1, gn1_scale, gn1_bias, p_a1, p_d1);
    bsplit_kernel<<<dim3(NTOT / 64, NBATCH), 256>>>(xs[0], xs[1], xs[2], xs[3], p_a1, p_d1, p_bg);

    cudaFuncSetAttribute(gemm_f16_kernel, cudaFuncAttributeMaxDynamicSharedMemorySize, 49152);
    gemm_f16_kernel<<<dim3(NCB, 2, NBATCH), 512, 49152>>>(p_ag, p_bg, b1, p_h, p_p2);

    finalize2_kernel<<<4 * NBATCH * NGROUP, 32>>>(p_p2, gn2_scale, gn2_bias, p_a2, p_d2);

    logits_kernel<<<dim3(NTOT / 256, NBATCH), 256>>>(p_h, p_a2, p_d2, W2, b2, p_log, outLog);

    const int tkSmem = (NTOT + NSEG) * 4;
    cudaFuncSetAttribute(topk_kernel, cudaFuncAttributeMaxDynamicSharedMemorySize, tkSmem);
    topk_kernel<<<NBATCH, 1024, tkSmem>>>(p_log, outIdF, outIdI);
}